// round 2
// baseline (speedup 1.0000x reference)
#include <cuda_runtime.h>
#include <cstdint>

typedef unsigned long long u64t;

#define T_STEPS 8192
#define DIM     2048
#define R_CTAS  128
#define R_THR   512   // 16 warps

// ---------------- scratch (no allocations allowed) ----------------
__device__ float    g_pre[(size_t)T_STEPS * DIM];   // 64 MB
__device__ float    g_h[2][DIM];
__device__ unsigned g_bar;

// ---------------- f32x2 helpers (sm_100+ packed fp32) ----------------
__device__ __forceinline__ u64t fma2(u64t a, u64t b, u64t c) {
    u64t d;
    asm("fma.rn.f32x2 %0, %1, %2, %3;" : "=l"(d) : "l"(a), "l"(b), "l"(c));
    return d;
}
__device__ __forceinline__ u64t add2(u64t a, u64t b) {
    u64t d;
    asm("add.rn.f32x2 %0, %1, %2;" : "=l"(d) : "l"(a), "l"(b));
    return d;
}
__device__ __forceinline__ u64t pk2(float lo, float hi) {
    u64t r;
    asm("mov.b64 %0, {%1, %2};" : "=l"(r) : "f"(lo), "f"(hi));
    return r;
}
__device__ __forceinline__ float sum2(u64t v) {
    float a, b;
    asm("mov.b64 {%0, %1}, %2;" : "=f"(a), "=f"(b) : "l"(v));
    return a + b;
}

// L2-coherent (cg) accesses: h ping-pong crosses SMs within one launch,
// and L1 is NOT coherent across SMs.
__device__ __forceinline__ ulonglong2 ldcg_v2u64(const ulonglong2* p) {
    ulonglong2 r;
    asm volatile("ld.global.cg.v2.u64 {%0, %1}, [%2];"
                 : "=l"(r.x), "=l"(r.y) : "l"(p));
    return r;
}
__device__ __forceinline__ float ldcg_f32(const float* p) {
    float r;
    asm volatile("ld.global.cg.f32 %0, [%1];" : "=f"(r) : "l"(p));
    return r;
}
__device__ __forceinline__ void stcg_f32(float* p, float v) {
    asm volatile("st.global.cg.f32 [%0], %1;" :: "l"(p), "f"(v));
}

// ---------------- init: reset barrier, seed h0 ----------------
__global__ void init_kernel(const float* __restrict__ h0) {
    int i = blockIdx.x * blockDim.x + threadIdx.x;
    if (i == 0) g_bar = 0u;
    if (i < DIM) g_h[0][i] = h0[i];
}

// ---------------- pre-GEMM: pre = x @ W1^T + b1 ----------------
// M=8192, N=2048, K=2048, both operands K-major. BM=BN=128, BK=16,
// 256 threads, 8x8 microtile as 2x2 blocks of 4x4. A is stored DUPLICATED
// ({v,v}) in smem so the f32x2 FMA needs no per-k packing MOVs; B pairs are
// natural (consecutive columns).
#define BM 128
#define BN 128
#define BK 16

__global__ void __launch_bounds__(256, 2)
gemm_pre_kernel(const float* __restrict__ X, const float* __restrict__ W1,
                const float* __restrict__ b1) {
    __shared__ u64t  Xd[BK * BM];     // 16 KB, duplicated floats
    __shared__ float Ws[BK * BN];     // 8 KB

    const int tid = threadIdx.x;
    const int tx = tid & 15;          // N direction (16)
    const int ty = tid >> 4;          // M direction (16)
    const int m0 = blockIdx.y * BM;
    const int n0 = blockIdx.x * BN;

    u64t acc[8][4];
#pragma unroll
    for (int i = 0; i < 8; i++)
#pragma unroll
        for (int j = 0; j < 4; j++) acc[i][j] = 0ull;

    for (int kt = 0; kt < DIM; kt += BK) {
        __syncthreads();
#pragma unroll
        for (int h = 0; h < 2; h++) {
            int idx = tid + h * 256;
            int k4  = idx & 3;         // which float4 along K
            int r   = idx >> 2;        // row within tile (0..127)
            float4 xv = *(const float4*)(X + (size_t)(m0 + r) * DIM + kt + k4 * 4);
            Xd[(k4 * 4 + 0) * BM + r] = pk2(xv.x, xv.x);
            Xd[(k4 * 4 + 1) * BM + r] = pk2(xv.y, xv.y);
            Xd[(k4 * 4 + 2) * BM + r] = pk2(xv.z, xv.z);
            Xd[(k4 * 4 + 3) * BM + r] = pk2(xv.w, xv.w);
            float4 wv = *(const float4*)(W1 + (size_t)(n0 + r) * DIM + kt + k4 * 4);
            Ws[(k4 * 4 + 0) * BN + r] = wv.x;
            Ws[(k4 * 4 + 1) * BN + r] = wv.y;
            Ws[(k4 * 4 + 2) * BN + r] = wv.z;
            Ws[(k4 * 4 + 3) * BN + r] = wv.w;
        }
        __syncthreads();

#pragma unroll
        for (int k = 0; k < BK; k++) {
            const u64t*  Xk = Xd + k * BM;
            const float* Wk = Ws + k * BN;
            u64t a[8];
            {
                ulonglong2 a0 = *(const ulonglong2*)(Xk + ty * 4);
                ulonglong2 a1 = *(const ulonglong2*)(Xk + ty * 4 + 2);
                ulonglong2 a2 = *(const ulonglong2*)(Xk + 64 + ty * 4);
                ulonglong2 a3 = *(const ulonglong2*)(Xk + 64 + ty * 4 + 2);
                a[0] = a0.x; a[1] = a0.y; a[2] = a1.x; a[3] = a1.y;
                a[4] = a2.x; a[5] = a2.y; a[6] = a3.x; a[7] = a3.y;
            }
            u64t bb[4];
            {
                ulonglong2 b0 = *(const ulonglong2*)(Wk + tx * 4);        // cols tx*4..+3
                ulonglong2 b1v = *(const ulonglong2*)(Wk + 64 + tx * 4);  // +64 group
                bb[0] = b0.x; bb[1] = b0.y; bb[2] = b1v.x; bb[3] = b1v.y;
            }
#pragma unroll
            for (int i = 0; i < 8; i++)
#pragma unroll
                for (int j = 0; j < 4; j++)
                    acc[i][j] = fma2(a[i], bb[j], acc[i][j]);
        }
    }

    // epilogue: += b1, store pairs
#pragma unroll
    for (int j = 0; j < 4; j++) {
        int col = n0 + ((j >> 1) * 64) + tx * 4 + (j & 1) * 2;
        u64t bp = pk2(b1[col], b1[col + 1]);
#pragma unroll
        for (int i = 0; i < 8; i++) {
            int row = m0 + ((i >> 2) * 64) + ty * 4 + (i & 3);
            u64t v = add2(acc[i][j], bp);
            *(u64t*)(g_pre + (size_t)row * DIM + col) = v;
        }
    }
}

// ---------------- recurrence: persistent kernel + software grid barrier ----
// 128 CTAs x 512 threads, 1 CTA/SM, all co-resident (128 < 148).
// CTA b owns output rows [16b, 16b+16). Warp w covers input cols
// [128w, 128w+128); lane = (row = l%16, half = l/16) -> 64 cols in REGISTERS
// (32 x u64 = 64 weights). Per step: 16 LDG.128 of broadcast h (lanes 0-15
// share addresses), 32 FFMA2, shfl+smem tree reduce, relu, stcg, grid barrier.
__global__ void __launch_bounds__(R_THR, 1)
recur_kernel(const float* __restrict__ W2, const float* __restrict__ b2) {
    const int tid  = threadIdx.x;
    const int w    = tid >> 5;
    const int l    = tid & 31;
    const int rowl = l & 15;
    const int half = l >> 4;
    const int rbase = blockIdx.x * 16;
    const int cbase = w * 128 + half * 64;

    u64t wreg[32];
    {
        const ulonglong2* wp =
            (const ulonglong2*)(W2 + (size_t)(rbase + rowl) * DIM + cbase);
#pragma unroll
        for (int i = 0; i < 16; i++) {
            ulonglong2 v = wp[i];
            wreg[2 * i]     = v.x;
            wreg[2 * i + 1] = v.y;
        }
    }
    const float b2r = b2[rbase + w];   // used by lane 0 of warp w
    const unsigned ncta = gridDim.x;

    __shared__ float part[16 * 17];

    for (int t = 0; t < T_STEPS; t++) {
        const int p = t & 1;
        float prev = 0.f;
        if (l == 0)   // consumer == producer: lane0 of warp w reduces row w
            prev = ldcg_f32(&g_pre[(size_t)t * DIM + rbase + w]);

        const ulonglong2* hp = (const ulonglong2*)(g_h[p] + cbase);
        u64t a0 = 0ull, a1 = 0ull;
#pragma unroll
        for (int i = 0; i < 16; i++) {
            ulonglong2 hv = ldcg_v2u64(hp + i);
            a0 = fma2(wreg[2 * i],     hv.x, a0);
            a1 = fma2(wreg[2 * i + 1], hv.y, a1);
        }
        float s = sum2(a0) + sum2(a1);
        s += __shfl_xor_sync(0xffffffffu, s, 16);
        if (half == 0) part[w * 17 + rowl] = s;
        __syncthreads();

        float v = (l < 16) ? part[l * 17 + w] : 0.f;
        v += __shfl_xor_sync(0xffffffffu, v, 8);
        v += __shfl_xor_sync(0xffffffffu, v, 4);
        v += __shfl_xor_sync(0xffffffffu, v, 2);
        v += __shfl_xor_sync(0xffffffffu, v, 1);
        if (l == 0) {
            float hnew = fmaxf(v + prev + b2r, 0.f);
            stcg_f32(&g_h[p ^ 1][rbase + w], hnew);
        }
        __syncthreads();                      // all h-stores issued CTA-wide

        if (tid == 0) {
            __threadfence();                  // release (cumulative via bar)
            atomicAdd(&g_bar, 1u);
            const unsigned tgt = (unsigned)(t + 1) * ncta;
            unsigned vb;
            do {
                asm volatile("ld.acquire.gpu.u32 %0, [%1];"
                             : "=r"(vb) : "l"(&g_bar) : "memory");
            } while (vb < tgt);
        }
        __syncthreads();                      // broadcast barrier pass
    }
}

// ---------------- head: out = h @ Wf^T + bf (1x4) ----------------
__global__ void final_kernel(const float* __restrict__ Wf,
                             const float* __restrict__ bf,
                             float* __restrict__ out) {
    const int w = threadIdx.x >> 5, l = threadIdx.x & 31;
    const float* h = g_h[0];                  // 8192 steps -> parity 0
    float s = 0.f;
    for (int d = l; d < DIM; d += 32)
        s += h[d] * Wf[(size_t)w * DIM + d];
    s += __shfl_xor_sync(0xffffffffu, s, 16);
    s += __shfl_xor_sync(0xffffffffu, s, 8);
    s += __shfl_xor_sync(0xffffffffu, s, 4);
    s += __shfl_xor_sync(0xffffffffu, s, 2);
    s += __shfl_xor_sync(0xffffffffu, s, 1);
    if (l == 0) out[w] = s + bf[w];
}

extern "C" void kernel_launch(void* const* d_in, const int* in_sizes, int n_in,
                              void* d_out, int out_size) {
    const float* x  = (const float*)d_in[0];
    const float* h0 = (const float*)d_in[1];
    const float* W1 = (const float*)d_in[2];
    const float* b1 = (const float*)d_in[3];
    const float* W2 = (const float*)d_in[4];
    const float* b2 = (const float*)d_in[5];
    const float* Wf = (const float*)d_in[6];
    const float* bf = (const float*)d_in[7];
    float* out = (float*)d_out;

    init_kernel<<<8, 256>>>(h0);
    dim3 gg(DIM / BN, T_STEPS / BM);          // (16, 64)
    gemm_pre_kernel<<<gg, 256>>>(x, W1, b1);
    recur_kernel<<<R_CTAS, R_THR>>>(W2, b2);
    final_kernel<<<1, 128>>>(Wf, bf, out);
}